// round 5
// baseline (speedup 1.0000x reference)
#include <cuda_runtime.h>
#include <cuda_bf16.h>
#include <cstdint>

// Problem constants (fixed by the benchmark's reference)
#define BB 4
#define TT 1024
#define VV 32000
#define ANS 512
#define TOPK 50
#define IGNORE_ID (-100)
#define NROWS 2048            // B*ANS rows per tensor
#define NBLK 74               // blocks per tensor in rowpass
#define ROWS_PER_BLK 28       // 74*28 = 2072 >= 2048
#define F4_PER_ROW 8000       // 32000/4
#define NCHUNK 32             // top-k chunks per tensor
#define CHUNK 1000            // vocab per chunk
#define CLU 8                 // cluster size for Sinkhorn

// ---------------- device scratch (static, no runtime alloc) ----------------
__device__ int   g_start[8];                    // [tensor][b]
__device__ int   g_size[8];
__device__ float g_stats[2 * NROWS * 4];        // inv, mg, rZ, valid
__device__ float g_partial[2 * NBLK * VV];      // per-block vocab partial sums
__device__ unsigned long long g_ck[2 * NCHUNK * TOPK];  // chunk candidate keys
__device__ int   g_order[2 * TOPK];
__device__ float g_q[2 * BB * ANS * TOPK];      // softmax(p/2) per tensor
__device__ float g_W[BB * 512 * 512];
__device__ float g_Km[BB * 512 * 512];
__device__ float g_part[32];

// ---------------- helpers --------------------------------------------------
__device__ __forceinline__ uint32_t smem_u32(const void* p) {
    uint32_t a;
    asm("{ .reg .u64 t; cvta.to.shared.u64 t, %1; cvt.u32.u64 %0, t; }"
        : "=r"(a) : "l"(p));
    return a;
}
__device__ __forceinline__ float ld_remote(const float* p, uint32_t rank) {
    uint32_t a = smem_u32(p), ra;
    asm("mapa.shared::cluster.u32 %0, %1, %2;" : "=r"(ra) : "r"(a), "r"(rank));
    float v;
    asm volatile("ld.shared::cluster.f32 %0, [%1];" : "=f"(v) : "r"(ra));
    return v;
}
#define CLUSTER_SYNC() do { \
    asm volatile("barrier.cluster.arrive.aligned;" ::: "memory"); \
    asm volatile("barrier.cluster.wait.aligned;"   ::: "memory"); } while (0)

// Monotone flip: ascending uint order == ascending float order.
__device__ __forceinline__ uint32_t fflip(float x) {
    uint32_t u = __float_as_uint(x);
    return u ^ ((u >> 31) ? 0xFFFFFFFFu : 0x80000000u);
}
// Key: ascending u64 order -> value DESC, tie -> index ASC (matches argsort(-v)).
__device__ __forceinline__ unsigned long long mkkey(float v, uint32_t idx) {
    return ((unsigned long long)(~fflip(v)) << 32) | (unsigned long long)idx;
}

// ---------------- kernel 0: answers (start/size per tensor,batch) ----------
__global__ void k_answers(const int* __restrict__ st, const int* __restrict__ tt) {
    int tid = threadIdx.x;
    int w = tid >> 5, l = tid & 31;
    if (w < 8) {
        int tensor = w >> 2, b = w & 3;
        const int* tg = (tensor ? tt : st) + b * TT;
        int first = 0x7fffffff, cnt = 0;
        for (int j = l; j < TT; j += 32) {
            if (tg[j] != IGNORE_ID) { cnt++; first = min(first, j); }
        }
        #pragma unroll
        for (int o = 16; o; o >>= 1) {
            cnt += __shfl_down_sync(0xffffffffu, cnt, o);
            first = min(first, __shfl_down_sync(0xffffffffu, first, o));
        }
        if (l == 0) {
            g_size[tensor * 4 + b] = cnt;
            g_start[tensor * 4 + b] = (cnt > 0) ? first : 0;
        }
    }
}

// ---------------- kernel 1: per-row stats + softmax + vocab partial sums ---
// L2 prefetch of the NEXT row is issued during the compute-only sweep 2, so
// DRAM stays busy while this row's exp/accumulate runs.
__global__ __launch_bounds__(1024, 1) void k_rowpass(const float* __restrict__ sl,
                                                     const float* __restrict__ tl) {
    extern __shared__ float4 smv[];            // 8000 float4 = 128000 B
    __shared__ float red[96];
    __shared__ float bc[4];
    const int tensor = blockIdx.x / NBLK;
    const int local  = blockIdx.x % NBLK;
    const float* __restrict__ logits = tensor ? tl : sl;
    const int tid = threadIdx.x;
    const int w = tid >> 5, l = tid & 31;

    float4 acc[8];
    #pragma unroll
    for (int k = 0; k < 8; k++) acc[k] = make_float4(0.f, 0.f, 0.f, 0.f);

    int r0 = local * ROWS_PER_BLK;
    int r1 = min(r0 + ROWS_PER_BLK, NROWS);

    for (int r = r0; r < r1; r++) {
        int b = r >> 9, pos = r & 511;
        int sz = g_size[tensor * 4 + b];
        if (pos >= sz) {
            if (tid == 0) {
                float* st = &g_stats[(tensor * NROWS + r) * 4];
                st[0] = 0.f; st[1] = 0.f; st[2] = 0.f; st[3] = 0.f;
            }
            continue;
        }
        int trow = g_start[tensor * 4 + b] + pos;
        trow = max(0, min(trow, TT - 1));
        const float4* __restrict__ src =
            (const float4*)(logits + (size_t)(b * TT + trow) * VV);

        // next-row pointer for L2 prefetch
        const float* nsrc = nullptr;
        {
            int nr = r + 1;
            if (nr < r1) {
                int bn = nr >> 9, posn = nr & 511;
                int szn = g_size[tensor * 4 + bn];
                if (posn < szn) {
                    int trn = g_start[tensor * 4 + bn] + posn;
                    trn = max(0, min(trn, TT - 1));
                    nsrc = logits + (size_t)(bn * TT + trn) * VV;
                }
            }
        }

        // sweep1: load row -> smem, stats
        float s = 0.f, q = 0.f, m = -3.402823466e38f;
        #pragma unroll
        for (int k = 0; k < 8; k++) {
            int f = tid + (k << 10);
            if (f < F4_PER_ROW) {
                float4 x = src[f];
                smv[f] = x;
                s += (x.x + x.y) + (x.z + x.w);
                q += (x.x * x.x + x.y * x.y) + (x.z * x.z + x.w * x.w);
                m = fmaxf(fmaxf(m, fmaxf(x.x, x.y)), fmaxf(x.z, x.w));
            }
        }
        #pragma unroll
        for (int o = 16; o; o >>= 1) {
            s += __shfl_down_sync(0xffffffffu, s, o);
            q += __shfl_down_sync(0xffffffffu, q, o);
            m = fmaxf(m, __shfl_down_sync(0xffffffffu, m, o));
        }
        if (l == 0) { red[w] = s; red[32 + w] = q; red[64 + w] = m; }
        __syncthreads();
        if (w == 0) {
            s = red[l]; q = red[32 + l]; m = red[64 + l];
            #pragma unroll
            for (int o = 16; o; o >>= 1) {
                s += __shfl_down_sync(0xffffffffu, s, o);
                q += __shfl_down_sync(0xffffffffu, q, o);
                m = fmaxf(m, __shfl_down_sync(0xffffffffu, m, o));
            }
            if (l == 0) {
                float var = (q - s * s * (1.f / (float)VV)) * (1.f / (float)(VV - 1));
                var = fmaxf(var, 0.f);
                float inv = 1.f / fmaxf(sqrtf(var), 1e-6f);
                bc[0] = inv; bc[1] = m * inv;
            }
        }
        __syncthreads();
        float inv = bc[0], mg = bc[1];

        // prefetch next row into L2 (1000 lines of 128B), overlapped with exp
        if (nsrc != nullptr && tid < 1000) {
            asm volatile("prefetch.global.L2 [%0];" :: "l"(nsrc + tid * 32));
        }

        // sweep2: exp in place, Z
        float z = 0.f;
        #pragma unroll
        for (int k = 0; k < 8; k++) {
            int f = tid + (k << 10);
            if (f < F4_PER_ROW) {
                float4 x = smv[f];
                x.x = __expf(fmaf(x.x, inv, -mg));
                x.y = __expf(fmaf(x.y, inv, -mg));
                x.z = __expf(fmaf(x.z, inv, -mg));
                x.w = __expf(fmaf(x.w, inv, -mg));
                smv[f] = x;
                z += (x.x + x.y) + (x.z + x.w);
            }
        }
        #pragma unroll
        for (int o = 16; o; o >>= 1) z += __shfl_down_sync(0xffffffffu, z, o);
        if (l == 0) red[w] = z;
        __syncthreads();
        if (w == 0) {
            z = red[l];
            #pragma unroll
            for (int o = 16; o; o >>= 1) z += __shfl_down_sync(0xffffffffu, z, o);
            if (l == 0) bc[2] = 1.f / z;
        }
        __syncthreads();
        float rZ = bc[2];

        // sweep3: accumulate probabilities into register accumulators
        #pragma unroll
        for (int k = 0; k < 8; k++) {
            int f = tid + (k << 10);
            if (f < F4_PER_ROW) {
                float4 e = smv[f];
                acc[k].x = fmaf(e.x, rZ, acc[k].x);
                acc[k].y = fmaf(e.y, rZ, acc[k].y);
                acc[k].z = fmaf(e.z, rZ, acc[k].z);
                acc[k].w = fmaf(e.w, rZ, acc[k].w);
            }
        }
        if (tid == 0) {
            float* st = &g_stats[(tensor * NROWS + r) * 4];
            st[0] = inv; st[1] = mg; st[2] = rZ; st[3] = 1.f;
        }
    }
    // flush deterministic per-block partials
    float4* gp = (float4*)&g_partial[(size_t)(tensor * NBLK + local) * VV];
    #pragma unroll
    for (int k = 0; k < 8; k++) {
        int f = tid + (k << 10);
        if (f < F4_PER_ROW) gp[f] = acc[k];
    }
}

// ---------------- kernel 2: chunk reduce + rank-select local top-50 --------
// grid = 2*NCHUNK blocks, 512 threads. Chunk c covers vocab [c*1000, (c+1)*1000).
// rank(i) = #{j : v[j] > v[i] || (v[j]==v[i] && j<i)}; top-50 = rank < 50,
// and the rank IS the output slot (exact stable argsort(-v) order).
__global__ __launch_bounds__(512, 2) void k_topk1() {
    __shared__ float sv[CHUNK];
    int t = blockIdx.x >> 5;
    int c = blockIdx.x & 31;
    int tid = threadIdx.x;
    int vbase = c * CHUNK;

    // reduce the 74 per-block partials (coalesced)
    #pragma unroll
    for (int k = 0; k < 2; k++) {
        int vl = tid + (k << 9);
        if (vl < CHUNK) {
            const float* p = &g_partial[(size_t)t * NBLK * VV + vbase + vl];
            float s = 0.f;
            #pragma unroll 2
            for (int lb = 0; lb < NBLK; lb++) s += p[(size_t)lb * VV];
            sv[vl] = s;
        }
    }
    __syncthreads();

    int   i0 = tid, i1 = tid + 512;
    bool  h0 = (i0 < CHUNK), h1 = (i1 < CHUNK);
    float v0 = h0 ? sv[i0] : 0.f;
    float v1 = h1 ? sv[i1] : 0.f;
    int r0 = 0, r1 = 0;
    #pragma unroll 4
    for (int j = 0; j < CHUNK; j++) {
        float x = sv[j];
        r0 += (x > v0) || (x == v0 && j < i0);
        r1 += (x > v1) || (x == v1 && j < i1);
    }
    if (h0 && r0 < TOPK) g_ck[(t * NCHUNK + c) * TOPK + r0] = mkkey(v0, (uint32_t)(vbase + i0));
    if (h1 && r1 < TOPK) g_ck[(t * NCHUNK + c) * TOPK + r1] = mkkey(v1, (uint32_t)(vbase + i1));
}

// ---------------- kernel 3: rank-select merge 1600 candidates -> top-50 ----
// Keys are unique (index in low bits) -> rank = #{j : key_j < key_i} is a
// permutation; rank < 50 gives the exact global sorted top-50.
__global__ __launch_bounds__(1024, 1) void k_topk2() {
    __shared__ unsigned long long keys[NCHUNK * TOPK];   // 1600
    int t = blockIdx.x;
    int tid = threadIdx.x;
    const int NC = NCHUNK * TOPK;
    if (tid < NC) keys[tid] = g_ck[t * NC + tid];
    if (tid + 1024 < NC) keys[tid + 1024] = g_ck[t * NC + tid + 1024];
    __syncthreads();
    unsigned long long k0 = (tid < NC) ? keys[tid] : ~0ull;
    unsigned long long k1 = (tid + 1024 < NC) ? keys[tid + 1024] : ~0ull;
    int r0 = 0, r1 = 0;
    #pragma unroll 4
    for (int j = 0; j < NC; j++) {
        unsigned long long x = keys[j];
        r0 += (x < k0);
        r1 += (x < k1);
    }
    if (tid < NC && r0 < TOPK)        g_order[t * TOPK + r0] = (int)(k0 & 0xFFFFFFFFull);
    if (tid + 1024 < NC && r1 < TOPK) g_order[t * TOPK + r1] = (int)(k1 & 0xFFFFFFFFull);
}

// ---------------- kernel 4: gather top-50 probs, softmax(p/2) --------------
__global__ void k_q(const float* __restrict__ sl, const float* __restrict__ tl) {
    __shared__ float sb[64];
    int id = blockIdx.x;
    int tensor = id >> 11;
    int r = id & 2047;
    int b = r >> 9, pos = r & 511;
    int tid = threadIdx.x;
    const float* __restrict__ logits = tensor ? tl : sl;
    const float* st = &g_stats[(tensor * NROWS + r) * 4];
    float inv = st[0], mg = st[1], rZ = st[2], val = st[3];
    int trow = g_start[tensor * 4 + b] + pos;
    trow = max(0, min(trow, TT - 1));
    float p = 0.f;
    if (tid < TOPK && val > 0.f) {
        int vv = g_order[tensor * TOPK + tid];
        float x = logits[(size_t)(b * TT + trow) * VV + vv];
        p = __expf(fmaf(x, inv, -mg)) * rZ;
    }
    float a = (tid < TOPK) ? 0.5f * p : -3.402823466e38f;   // /SINK_T
    sb[tid] = a; __syncthreads();
    for (int o = 32; o; o >>= 1) { if (tid < o) sb[tid] = fmaxf(sb[tid], sb[tid + o]); __syncthreads(); }
    float amax = sb[0]; __syncthreads();
    float e = (tid < TOPK) ? __expf(a - amax) : 0.f;
    sb[tid] = e; __syncthreads();
    for (int o = 32; o; o >>= 1) { if (tid < o) sb[tid] = sb[tid] + sb[tid + o]; __syncthreads(); }
    float ssum = sb[0];
    if (tid < TOPK)
        g_q[((size_t)(tensor * BB + b) * ANS + pos) * TOPK + tid] = e / ssum;
}

// ---------------- kernel 5: W, K=max(exp(-2W),1e-30) -----------------------
__device__ __forceinline__ float expK(float wv) {
    return fmaxf(__expf(-2.f * wv), 1e-30f);
}
__global__ void k_W() {
    __shared__ float xs[TOPK][64];
    __shared__ float ys[TOPK][64];
    int b = blockIdx.z;
    int i0 = blockIdx.x * 64, j0 = blockIdx.y * 64;
    int tx = threadIdx.x, ty = threadIdx.y;
    int tid = ty * 16 + tx;
    for (int e = tid; e < 64 * TOPK; e += 256) {
        int rr = e / TOPK, kk = e - rr * TOPK;
        xs[kk][rr] = g_q[((size_t)(0 * BB + b) * ANS + (i0 + rr)) * TOPK + kk];
        ys[kk][rr] = g_q[((size_t)(1 * BB + b) * ANS + (j0 + rr)) * TOPK + kk];
    }
    __syncthreads();
    float acc[4][4];
    #pragma unroll
    for (int i = 0; i < 4; i++)
        #pragma unroll
        for (int j = 0; j < 4; j++) acc[i][j] = 0.f;
    for (int k = 0; k < TOPK; k++) {
        float4 a = *(const float4*)&xs[k][tx * 4];
        float4 c = *(const float4*)&ys[k][ty * 4];
        acc[0][0] += fabsf(a.x - c.x); acc[0][1] += fabsf(a.x - c.y);
        acc[0][2] += fabsf(a.x - c.z); acc[0][3] += fabsf(a.x - c.w);
        acc[1][0] += fabsf(a.y - c.x); acc[1][1] += fabsf(a.y - c.y);
        acc[1][2] += fabsf(a.y - c.z); acc[1][3] += fabsf(a.y - c.w);
        acc[2][0] += fabsf(a.z - c.x); acc[2][1] += fabsf(a.z - c.y);
        acc[2][2] += fabsf(a.z - c.z); acc[2][3] += fabsf(a.z - c.w);
        acc[3][0] += fabsf(a.w - c.x); acc[3][1] += fabsf(a.w - c.y);
        acc[3][2] += fabsf(a.w - c.z); acc[3][3] += fabsf(a.w - c.w);
    }
    #pragma unroll
    for (int ii = 0; ii < 4; ii++) {
        int i = i0 + tx * 4 + ii;
        float4 wv = make_float4(acc[ii][0], acc[ii][1], acc[ii][2], acc[ii][3]);
        size_t base = ((size_t)(b * 512) + i) * 512 + j0 + ty * 4;
        *(float4*)&g_W[base] = wv;
        *(float4*)&g_Km[base] = make_float4(expK(wv.x), expK(wv.y), expK(wv.z), expK(wv.w));
    }
}

// ---------------- kernel 6: fused Sinkhorn (10 iters) + loss ---------------
// Grid: 32 blocks = 4 batches x 8-CTA clusters. Each CTA owns 64 rows of K.
// Only the OWN u segment is ever needed (u-step, v-partial, loss), so no
// u exchange; v is rebuilt redundantly per CTA from DSMEM ps partials.
// 2 cluster syncs per iteration: ps-publish, ps-consume (WAR guard).
__global__ __cluster_dims__(CLU, 1, 1) __launch_bounds__(512, 1)
void k_sink() {
    extern __shared__ float sm[];
    float* Ks = sm;                 // 64*512 = 32768 floats (own K rows)
    float* us = sm + 32768;         // 512 (only own 64-segment used)
    float* vs = sm + 33280;         // 512
    float* ps = sm + 33792;         // 512 (partial for v-step)
    __shared__ float lred[16];

    uint32_t rank;
    asm("mov.u32 %0, %%cluster_ctarank;" : "=r"(rank));
    int b = blockIdx.x >> 3;
    int tid = threadIdx.x;
    int w = tid >> 5, l = tid & 31;

    // load own K block (rows [rank*64, rank*64+64))
    const float4* src = (const float4*)(g_Km + ((size_t)(b * 512) + rank * 64) * 512);
    float4* dst = (float4*)Ks;
    for (int i = tid; i < 64 * 512 / 4; i += 512) dst[i] = src[i];
    us[tid] = 1.f; vs[tid] = 1.f;
    __syncthreads();

    for (int it = 0; it < 10; it++) {
        // ---- u-step (own rows): u_i <- u_i / max(u_i*(K v)_i, 1e-10)
        #pragma unroll
        for (int rr = 0; rr < 4; rr++) {
            int i = w * 4 + rr;                       // local row 0..63
            const float4* row = (const float4*)(Ks + i * 512);
            float d = 0.f;
            #pragma unroll
            for (int c = 0; c < 4; c++) {
                int f = l + (c << 5);
                float4 kv = row[f];
                int j = f << 2;
                d += kv.x * vs[j] + kv.y * vs[j + 1] + kv.z * vs[j + 2] + kv.w * vs[j + 3];
            }
            #pragma unroll
            for (int o = 16; o; o >>= 1) d += __shfl_down_sync(0xffffffffu, d, o);
            if (l == 0) {
                int gi = rank * 64 + i;
                float uu = us[gi];
                us[gi] = uu / fmaxf(uu * d, 1e-10f);
            }
        }
        __syncthreads();
        // ---- v-step partial: ps[j] = sum_{i in own rows} K[i][j] * u[own i]
        {
            float s = 0.f;
            #pragma unroll 8
            for (int i = 0; i < 64; i++)
                s = fmaf(Ks[i * 512 + tid], us[rank * 64 + i], s);
            ps[tid] = s;
        }
        __syncthreads();
        CLUSTER_SYNC();                               // publish ps to cluster
        // ---- v-reduce (each CTA redundantly computes full new v)
        {
            float s = ps[tid];
            #pragma unroll
            for (int c = 0; c < CLU; c++) {
                if ((uint32_t)c != rank) s += ld_remote(&ps[tid], (uint32_t)c);
            }
            float vv = vs[tid];
            vs[tid] = vv / fmaxf(vv * s, 1e-10f);
        }
        CLUSTER_SYNC();                               // all remote ps reads done
    }

    // ---- loss: sum over own rows of u_i * K_ij * W_ij * v_j
    const float* Wg = g_W + ((size_t)(b * 512) + rank * 64) * 512;
    float lacc = 0.f;
    #pragma unroll
    for (int rr = 0; rr < 4; rr++) {
        int i = w * 4 + rr;
        const float4* rowK = (const float4*)(Ks + i * 512);
        const float4* rowW = (const float4*)(Wg + (size_t)i * 512);
        float d = 0.f;
        #pragma unroll
        for (int c = 0; c < 4; c++) {
            int f = l + (c << 5);
            float4 kv = rowK[f];
            float4 wv = rowW[f];
            int j = f << 2;
            d += kv.x * wv.x * vs[j] + kv.y * wv.y * vs[j + 1]
               + kv.z * wv.z * vs[j + 2] + kv.w * wv.w * vs[j + 3];
        }
        #pragma unroll
        for (int o = 16; o; o >>= 1) d += __shfl_down_sync(0xffffffffu, d, o);
        if (l == 0) lacc += us[rank * 64 + i] * d;
    }
    if (l == 0) lred[w] = lacc;
    __syncthreads();
    if (tid == 0) {
        float s = 0.f;
        #pragma unroll
        for (int k = 0; k < 16; k++) s += lred[k];
        g_part[blockIdx.x] = s;
    }
    CLUSTER_SYNC();   // no CTA exits while peers may still read its smem
}

// ---------------- kernel 7: final scalar -----------------------------------
__global__ void k_final(const float* __restrict__ ce, float* __restrict__ out) {
    float s = 0.f;
    for (int i = 0; i < 32; i++) s += g_part[i];
    out[0] = ce[0] + 0.001f * s;   // CE_W=1, KD_W=1
}

// ---------------- launcher -------------------------------------------------
extern "C" void kernel_launch(void* const* d_in, const int* in_sizes, int n_in,
                              void* d_out, int out_size) {
    const float* sl  = (const float*)d_in[0];
    const float* tl  = (const float*)d_in[1];
    const float* ce  = (const float*)d_in[2];
    const int*   stt = (const int*)d_in[3];
    const int*   ttt = (const int*)d_in[4];
    float* out = (float*)d_out;

    static bool attr_done = false;
    if (!attr_done) {
        cudaFuncSetAttribute(k_rowpass, cudaFuncAttributeMaxDynamicSharedMemorySize, 128000);
        cudaFuncSetAttribute(k_sink,    cudaFuncAttributeMaxDynamicSharedMemorySize, 34304 * 4);
        attr_done = true;
    }

    k_answers<<<1, 256>>>(stt, ttt);
    k_rowpass<<<2 * NBLK, 1024, 128000>>>(sl, tl);
    k_topk1<<<2 * NCHUNK, 512>>>();
    k_topk2<<<2, 1024>>>();
    k_q<<<2 * NROWS, 64>>>(sl, tl);
    k_W<<<dim3(8, 8, BB), dim3(16, 16)>>>();
    k_sink<<<32, 512, 34304 * 4>>>();
    k_final<<<1, 1>>>(ce, out);
}

// round 6
// speedup vs baseline: 1.1451x; 1.1451x over previous
#include <cuda_runtime.h>
#include <cuda_bf16.h>
#include <cstdint>

// Problem constants (fixed by the benchmark's reference)
#define BB 4
#define TT 1024
#define VV 32000
#define ANS 512
#define TOPK 50
#define IGNORE_ID (-100)
#define NROWS 2048            // B*ANS rows per tensor
#define NBLK 74               // blocks per tensor in rowpass
#define ROWS_PER_BLK 28       // 74*28 = 2072 >= 2048
#define F4_PER_ROW 8000       // 32000/4
#define NCHUNK 32             // top-k chunks per tensor
#define CHUNK 1000            // vocab per chunk
#define CLU 8                 // cluster size for Sinkhorn

// ---------------- device scratch (static, no runtime alloc) ----------------
__device__ int   g_start[8];                    // [tensor][b]
__device__ int   g_size[8];
__device__ float g_stats[2 * NROWS * 4];        // inv, mg, rZ, valid
__device__ float g_partial[2 * NBLK * VV];      // per-block vocab partial sums
__device__ unsigned long long g_ck[2 * NCHUNK * TOPK];  // chunk candidate keys
__device__ int   g_order[2 * TOPK];
__device__ float g_q[2 * BB * ANS * TOPK];      // softmax(p/2) per tensor
__device__ float g_W[BB * 512 * 512];
__device__ float g_Km[BB * 512 * 512];
__device__ float g_part[32];

// ---------------- helpers --------------------------------------------------
__device__ __forceinline__ uint32_t smem_u32(const void* p) {
    uint32_t a;
    asm("{ .reg .u64 t; cvta.to.shared.u64 t, %1; cvt.u32.u64 %0, t; }"
        : "=r"(a) : "l"(p));
    return a;
}
__device__ __forceinline__ float ld_remote(const float* p, uint32_t rank) {
    uint32_t a = smem_u32(p), ra;
    asm("mapa.shared::cluster.u32 %0, %1, %2;" : "=r"(ra) : "r"(a), "r"(rank));
    float v;
    asm volatile("ld.shared::cluster.f32 %0, [%1];" : "=f"(v) : "r"(ra));
    return v;
}
#define CLUSTER_SYNC() do { \
    asm volatile("barrier.cluster.arrive.aligned;" ::: "memory"); \
    asm volatile("barrier.cluster.wait.aligned;"   ::: "memory"); } while (0)

// Monotone flip: ascending uint order == ascending float order.
__device__ __forceinline__ uint32_t fflip(float x) {
    uint32_t u = __float_as_uint(x);
    return u ^ ((u >> 31) ? 0xFFFFFFFFu : 0x80000000u);
}
// Key: ascending u64 order -> value DESC, tie -> index ASC (matches argsort(-v)).
__device__ __forceinline__ unsigned long long mkkey(float v, uint32_t idx) {
    return ((unsigned long long)(~fflip(v)) << 32) | (unsigned long long)idx;
}

// Bitonic sort over smem keys. T threads, N = 2T keys.
template<int N, int T>
__device__ __forceinline__ void bitonic_sort(unsigned long long* keys, int t) {
    #pragma unroll 1
    for (int k = 2; k <= N; k <<= 1) {
        #pragma unroll 1
        for (int j = k >> 1; j > 0; j >>= 1) {
            int lo = t & (j - 1);
            int i  = ((t - lo) << 1) + lo;
            int p  = i | j;
            bool up = ((i & k) == 0);
            unsigned long long a = keys[i], b = keys[p];
            bool sw = up ? (a > b) : (a < b);
            if (sw) { keys[i] = b; keys[p] = a; }
            __syncthreads();
        }
    }
}

// ---------------- no-op kernel (profiler launch-index alignment) -----------
__global__ void k_nop() {}

// ---------------- kernel 0: answers (start/size per tensor,batch) ----------
__global__ void k_answers(const int* __restrict__ st, const int* __restrict__ tt) {
    int tid = threadIdx.x;
    int w = tid >> 5, l = tid & 31;
    if (w < 8) {
        int tensor = w >> 2, b = w & 3;
        const int* tg = (tensor ? tt : st) + b * TT;
        int first = 0x7fffffff, cnt = 0;
        for (int j = l; j < TT; j += 32) {
            if (tg[j] != IGNORE_ID) { cnt++; first = min(first, j); }
        }
        #pragma unroll
        for (int o = 16; o; o >>= 1) {
            cnt += __shfl_down_sync(0xffffffffu, cnt, o);
            first = min(first, __shfl_down_sync(0xffffffffu, first, o));
        }
        if (l == 0) {
            g_size[tensor * 4 + b] = cnt;
            g_start[tensor * 4 + b] = (cnt > 0) ? first : 0;
        }
    }
}

// ---------------- kernel 1: per-row stats + softmax + vocab partial sums ---
// Pipelined: the previous row's probability accumulation (acc += e * rZ_prev)
// is deferred and executed UNDER the next row's global-load latency. Each
// smem slot f = tid + k*1024 is touched by exactly one thread, so the
// consume-then-overwrite sequence needs no barrier.
__global__ __launch_bounds__(1024, 1) void k_rowpass(const float* __restrict__ sl,
                                                     const float* __restrict__ tl) {
    extern __shared__ float4 smv[];            // 8000 float4 = 128000 B
    __shared__ float red[96];
    __shared__ float bc[4];
    const int tensor = blockIdx.x / NBLK;
    const int local  = blockIdx.x % NBLK;
    const float* __restrict__ logits = tensor ? tl : sl;
    const int tid = threadIdx.x;
    const int w = tid >> 5, l = tid & 31;

    float4 acc[8];
    #pragma unroll
    for (int k = 0; k < 8; k++) acc[k] = make_float4(0.f, 0.f, 0.f, 0.f);

    int r0 = local * ROWS_PER_BLK;
    int r1 = min(r0 + ROWS_PER_BLK, NROWS);

    float prZ = 0.f;
    bool  pend = false;

    for (int r = r0; r < r1; r++) {
        int b = r >> 9, pos = r & 511;
        int sz = g_size[tensor * 4 + b];
        if (pos >= sz) {
            if (tid == 0) {
                float* st = &g_stats[(tensor * NROWS + r) * 4];
                st[0] = 0.f; st[1] = 0.f; st[2] = 0.f; st[3] = 0.f;
            }
            continue;
        }
        int trow = g_start[tensor * 4 + b] + pos;
        trow = max(0, min(trow, TT - 1));
        const float4* __restrict__ src =
            (const float4*)(logits + (size_t)(b * TT + trow) * VV);

        // issue this row's loads first (deep MLP), ...
        float4 x[8];
        #pragma unroll
        for (int k = 0; k < 8; k++) {
            int f = tid + (k << 10);
            if (f < F4_PER_ROW) x[k] = src[f];
        }
        // ... consume the previous row's probabilities under the load shadow
        if (pend) {
            #pragma unroll
            for (int k = 0; k < 8; k++) {
                int f = tid + (k << 10);
                if (f < F4_PER_ROW) {
                    float4 e = smv[f];
                    acc[k].x = fmaf(e.x, prZ, acc[k].x);
                    acc[k].y = fmaf(e.y, prZ, acc[k].y);
                    acc[k].z = fmaf(e.z, prZ, acc[k].z);
                    acc[k].w = fmaf(e.w, prZ, acc[k].w);
                }
            }
            pend = false;
        }

        // stats + stage raw row to smem
        float s = 0.f, q = 0.f, m = -3.402823466e38f;
        #pragma unroll
        for (int k = 0; k < 8; k++) {
            int f = tid + (k << 10);
            if (f < F4_PER_ROW) {
                float4 xx = x[k];
                smv[f] = xx;
                s += (xx.x + xx.y) + (xx.z + xx.w);
                q += (xx.x * xx.x + xx.y * xx.y) + (xx.z * xx.z + xx.w * xx.w);
                m = fmaxf(fmaxf(m, fmaxf(xx.x, xx.y)), fmaxf(xx.z, xx.w));
            }
        }
        #pragma unroll
        for (int o = 16; o; o >>= 1) {
            s += __shfl_down_sync(0xffffffffu, s, o);
            q += __shfl_down_sync(0xffffffffu, q, o);
            m = fmaxf(m, __shfl_down_sync(0xffffffffu, m, o));
        }
        if (l == 0) { red[w] = s; red[32 + w] = q; red[64 + w] = m; }
        __syncthreads();
        if (w == 0) {
            s = red[l]; q = red[32 + l]; m = red[64 + l];
            #pragma unroll
            for (int o = 16; o; o >>= 1) {
                s += __shfl_down_sync(0xffffffffu, s, o);
                q += __shfl_down_sync(0xffffffffu, q, o);
                m = fmaxf(m, __shfl_down_sync(0xffffffffu, m, o));
            }
            if (l == 0) {
                float var = (q - s * s * (1.f / (float)VV)) * (1.f / (float)(VV - 1));
                var = fmaxf(var, 0.f);
                float inv = 1.f / fmaxf(sqrtf(var), 1e-6f);
                bc[0] = inv; bc[1] = m * inv;
            }
        }
        __syncthreads();
        float inv = bc[0], mg = bc[1];

        // sweep2: exp in place (e kept in smem for deferred accumulation), Z
        float z = 0.f;
        #pragma unroll
        for (int k = 0; k < 8; k++) {
            int f = tid + (k << 10);
            if (f < F4_PER_ROW) {
                float4 xx = smv[f];
                xx.x = __expf(fmaf(xx.x, inv, -mg));
                xx.y = __expf(fmaf(xx.y, inv, -mg));
                xx.z = __expf(fmaf(xx.z, inv, -mg));
                xx.w = __expf(fmaf(xx.w, inv, -mg));
                smv[f] = xx;
                z += (xx.x + xx.y) + (xx.z + xx.w);
            }
        }
        #pragma unroll
        for (int o = 16; o; o >>= 1) z += __shfl_down_sync(0xffffffffu, z, o);
        if (l == 0) red[w] = z;
        __syncthreads();
        if (w == 0) {
            z = red[l];
            #pragma unroll
            for (int o = 16; o; o >>= 1) z += __shfl_down_sync(0xffffffffu, z, o);
            if (l == 0) bc[2] = 1.f / z;
        }
        __syncthreads();
        float rZ = bc[2];
        prZ = rZ;
        pend = true;

        if (tid == 0) {
            float* st = &g_stats[(tensor * NROWS + r) * 4];
            st[0] = inv; st[1] = mg; st[2] = rZ; st[3] = 1.f;
        }
    }
    // epilogue: consume the last pending row
    if (pend) {
        #pragma unroll
        for (int k = 0; k < 8; k++) {
            int f = tid + (k << 10);
            if (f < F4_PER_ROW) {
                float4 e = smv[f];
                acc[k].x = fmaf(e.x, prZ, acc[k].x);
                acc[k].y = fmaf(e.y, prZ, acc[k].y);
                acc[k].z = fmaf(e.z, prZ, acc[k].z);
                acc[k].w = fmaf(e.w, prZ, acc[k].w);
            }
        }
    }
    // flush deterministic per-block partials
    float4* gp = (float4*)&g_partial[(size_t)(tensor * NBLK + local) * VV];
    #pragma unroll
    for (int k = 0; k < 8; k++) {
        int f = tid + (k << 10);
        if (f < F4_PER_ROW) gp[f] = acc[k];
    }
}

// ---------------- kernel 2: chunk reduce + bitonic local top-50 ------------
// grid = 2*NCHUNK blocks, 512 threads. Chunk c covers vocab [c*1000, (c+1)*1000).
__global__ __launch_bounds__(512, 2) void k_topk1() {
    __shared__ unsigned long long keys[1024];
    int t = blockIdx.x >> 5;
    int c = blockIdx.x & 31;
    int tid = threadIdx.x;
    int vbase = c * CHUNK;

    // reduce the 74 per-block partials (coalesced) and build keys
    #pragma unroll
    for (int k = 0; k < 2; k++) {
        int vl = tid + (k << 9);
        if (vl < CHUNK) {
            const float* p = &g_partial[(size_t)t * NBLK * VV + vbase + vl];
            float s = 0.f;
            #pragma unroll 2
            for (int lb = 0; lb < NBLK; lb++) s += p[(size_t)lb * VV];
            keys[vl] = mkkey(s, (uint32_t)(vbase + vl));
        } else {
            keys[vl] = 0xFFFFFFFFFFFFFFFFull;   // pad: sorts last
        }
    }
    __syncthreads();
    bitonic_sort<1024, 512>(keys, tid);
    if (tid < TOPK)
        g_ck[(t * NCHUNK + c) * TOPK + tid] = keys[tid];
}

// ---------------- kernel 3: bitonic merge 1600 candidates -> top-50 --------
__global__ __launch_bounds__(1024, 1) void k_topk2() {
    __shared__ unsigned long long keys[2048];
    int t = blockIdx.x;
    int tid = threadIdx.x;
    const int NC = NCHUNK * TOPK;   // 1600
    #pragma unroll
    for (int k = 0; k < 2; k++) {
        int s = tid + (k << 10);
        keys[s] = (s < NC) ? g_ck[t * NC + s] : 0xFFFFFFFFFFFFFFFFull;
    }
    __syncthreads();
    bitonic_sort<2048, 1024>(keys, tid);
    if (tid < TOPK)
        g_order[t * TOPK + tid] = (int)(keys[tid] & 0xFFFFFFFFull);
}

// ---------------- kernel 4: gather top-50 probs, softmax(p/2) --------------
__global__ void k_q(const float* __restrict__ sl, const float* __restrict__ tl) {
    __shared__ float sb[64];
    int id = blockIdx.x;
    int tensor = id >> 11;
    int r = id & 2047;
    int b = r >> 9, pos = r & 511;
    int tid = threadIdx.x;
    const float* __restrict__ logits = tensor ? tl : sl;
    const float* st = &g_stats[(tensor * NROWS + r) * 4];
    float inv = st[0], mg = st[1], rZ = st[2], val = st[3];
    int trow = g_start[tensor * 4 + b] + pos;
    trow = max(0, min(trow, TT - 1));
    float p = 0.f;
    if (tid < TOPK && val > 0.f) {
        int vv = g_order[tensor * TOPK + tid];
        float x = logits[(size_t)(b * TT + trow) * VV + vv];
        p = __expf(fmaf(x, inv, -mg)) * rZ;
    }
    float a = (tid < TOPK) ? 0.5f * p : -3.402823466e38f;   // /SINK_T
    sb[tid] = a; __syncthreads();
    for (int o = 32; o; o >>= 1) { if (tid < o) sb[tid] = fmaxf(sb[tid], sb[tid + o]); __syncthreads(); }
    float amax = sb[0]; __syncthreads();
    float e = (tid < TOPK) ? __expf(a - amax) : 0.f;
    sb[tid] = e; __syncthreads();
    for (int o = 32; o; o >>= 1) { if (tid < o) sb[tid] = sb[tid] + sb[tid + o]; __syncthreads(); }
    float ssum = sb[0];
    if (tid < TOPK)
        g_q[((size_t)(tensor * BB + b) * ANS + pos) * TOPK + tid] = e / ssum;
}

// ---------------- kernel 5: W, K=max(exp(-2W),1e-30) -----------------------
__device__ __forceinline__ float expK(float wv) {
    return fmaxf(__expf(-2.f * wv), 1e-30f);
}
__global__ void k_W() {
    __shared__ float xs[TOPK][64];
    __shared__ float ys[TOPK][64];
    int b = blockIdx.z;
    int i0 = blockIdx.x * 64, j0 = blockIdx.y * 64;
    int tx = threadIdx.x, ty = threadIdx.y;
    int tid = ty * 16 + tx;
    for (int e = tid; e < 64 * TOPK; e += 256) {
        int rr = e / TOPK, kk = e - rr * TOPK;
        xs[kk][rr] = g_q[((size_t)(0 * BB + b) * ANS + (i0 + rr)) * TOPK + kk];
        ys[kk][rr] = g_q[((size_t)(1 * BB + b) * ANS + (j0 + rr)) * TOPK + kk];
    }
    __syncthreads();
    float acc[4][4];
    #pragma unroll
    for (int i = 0; i < 4; i++)
        #pragma unroll
        for (int j = 0; j < 4; j++) acc[i][j] = 0.f;
    for (int k = 0; k < TOPK; k++) {
        float4 a = *(const float4*)&xs[k][tx * 4];
        float4 c = *(const float4*)&ys[k][ty * 4];
        acc[0][0] += fabsf(a.x - c.x); acc[0][1] += fabsf(a.x - c.y);
        acc[0][2] += fabsf(a.x - c.z); acc[0][3] += fabsf(a.x - c.w);
        acc[1][0] += fabsf(a.y - c.x); acc[1][1] += fabsf(a.y - c.y);
        acc[1][2] += fabsf(a.y - c.z); acc[1][3] += fabsf(a.y - c.w);
        acc[2][0] += fabsf(a.z - c.x); acc[2][1] += fabsf(a.z - c.y);
        acc[2][2] += fabsf(a.z - c.z); acc[2][3] += fabsf(a.z - c.w);
        acc[3][0] += fabsf(a.w - c.x); acc[3][1] += fabsf(a.w - c.y);
        acc[3][2] += fabsf(a.w - c.z); acc[3][3] += fabsf(a.w - c.w);
    }
    #pragma unroll
    for (int ii = 0; ii < 4; ii++) {
        int i = i0 + tx * 4 + ii;
        float4 wv = make_float4(acc[ii][0], acc[ii][1], acc[ii][2], acc[ii][3]);
        size_t base = ((size_t)(b * 512) + i) * 512 + j0 + ty * 4;
        *(float4*)&g_W[base] = wv;
        *(float4*)&g_Km[base] = make_float4(expK(wv.x), expK(wv.y), expK(wv.z), expK(wv.w));
    }
}

// ---------------- kernel 6: fused Sinkhorn (10 iters) + loss ---------------
// Grid: 32 blocks = 4 batches x 8-CTA clusters. Each CTA owns 64 rows of K.
// Only the OWN u segment is ever needed (u-step, v-partial, loss), so no
// u exchange; v is rebuilt redundantly per CTA from DSMEM ps partials.
__global__ __cluster_dims__(CLU, 1, 1) __launch_bounds__(512, 1)
void k_sink() {
    extern __shared__ float sm[];
    float* Ks = sm;                 // 64*512 = 32768 floats (own K rows)
    float* us = sm + 32768;         // 512 (only own 64-segment used)
    float* vs = sm + 33280;         // 512
    float* ps = sm + 33792;         // 512 (partial for v-step)
    __shared__ float lred[16];

    uint32_t rank;
    asm("mov.u32 %0, %%cluster_ctarank;" : "=r"(rank));
    int b = blockIdx.x >> 3;
    int tid = threadIdx.x;
    int w = tid >> 5, l = tid & 31;

    // load own K block (rows [rank*64, rank*64+64))
    const float4* src = (const float4*)(g_Km + ((size_t)(b * 512) + rank * 64) * 512);
    float4* dst = (float4*)Ks;
    for (int i = tid; i < 64 * 512 / 4; i += 512) dst[i] = src[i];
    us[tid] = 1.f; vs[tid] = 1.f;
    __syncthreads();

    for (int it = 0; it < 10; it++) {
        // ---- u-step (own rows): u_i <- u_i / max(u_i*(K v)_i, 1e-10)
        #pragma unroll
        for (int rr = 0; rr < 4; rr++) {
            int i = w * 4 + rr;                       // local row 0..63
            const float4* row = (const float4*)(Ks + i * 512);
            float d = 0.f;
            #pragma unroll
            for (int c = 0; c < 4; c++) {
                int f = l + (c << 5);
                float4 kv = row[f];
                int j = f << 2;
                d += kv.x * vs[j] + kv.y * vs[j + 1] + kv.z * vs[j + 2] + kv.w * vs[j + 3];
            }
            #pragma unroll
            for (int o = 16; o; o >>= 1) d += __shfl_down_sync(0xffffffffu, d, o);
            if (l == 0) {
                int gi = rank * 64 + i;
                float uu = us[gi];
                us[gi] = uu / fmaxf(uu * d, 1e-10f);
            }
        }
        __syncthreads();
        // ---- v-step partial: ps[j] = sum_{i in own rows} K[i][j] * u[own i]
        {
            float s = 0.f;
            #pragma unroll 8
            for (int i = 0; i < 64; i++)
                s = fmaf(Ks[i * 512 + tid], us[rank * 64 + i], s);
            ps[tid] = s;
        }
        __syncthreads();
        CLUSTER_SYNC();                               // publish ps to cluster
        // ---- v-reduce (each CTA redundantly computes full new v)
        {
            float s = ps[tid];
            #pragma unroll
            for (int c = 0; c < CLU; c++) {
                if ((uint32_t)c != rank) s += ld_remote(&ps[tid], (uint32_t)c);
            }
            float vv = vs[tid];
            vs[tid] = vv / fmaxf(vv * s, 1e-10f);
        }
        CLUSTER_SYNC();                               // all remote ps reads done
    }

    // ---- loss: sum over own rows of u_i * K_ij * W_ij * v_j
    const float* Wg = g_W + ((size_t)(b * 512) + rank * 64) * 512;
    float lacc = 0.f;
    #pragma unroll
    for (int rr = 0; rr < 4; rr++) {
        int i = w * 4 + rr;
        const float4* rowK = (const float4*)(Ks + i * 512);
        const float4* rowW = (const float4*)(Wg + (size_t)i * 512);
        float d = 0.f;
        #pragma unroll
        for (int c = 0; c < 4; c++) {
            int f = l + (c << 5);
            float4 kv = rowK[f];
            float4 wv = rowW[f];
            int j = f << 2;
            d += kv.x * wv.x * vs[j] + kv.y * wv.y * vs[j + 1]
               + kv.z * wv.z * vs[j + 2] + kv.w * wv.w * vs[j + 3];
        }
        #pragma unroll
        for (int o = 16; o; o >>= 1) d += __shfl_down_sync(0xffffffffu, d, o);
        if (l == 0) lacc += us[rank * 64 + i] * d;
    }
    if (l == 0) lred[w] = lacc;
    __syncthreads();
    if (tid == 0) {
        float s = 0.f;
        #pragma unroll
        for (int k = 0; k < 16; k++) s += lred[k];
        g_part[blockIdx.x] = s;
    }
    CLUSTER_SYNC();   // no CTA exits while peers may still read its smem
}

// ---------------- kernel 7: final scalar -----------------------------------
__global__ void k_final(const float* __restrict__ ce, float* __restrict__ out) {
    float s = 0.f;
    for (int i = 0; i < 32; i++) s += g_part[i];
    out[0] = ce[0] + 0.001f * s;   // CE_W=1, KD_W=1
}

// ---------------- launcher -------------------------------------------------
extern "C" void kernel_launch(void* const* d_in, const int* in_sizes, int n_in,
                              void* d_out, int out_size) {
    const float* sl  = (const float*)d_in[0];
    const float* tl  = (const float*)d_in[1];
    const float* ce  = (const float*)d_in[2];
    const int*   stt = (const int*)d_in[3];
    const int*   ttt = (const int*)d_in[4];
    float* out = (float*)d_out;

    static bool attr_done = false;
    if (!attr_done) {
        cudaFuncSetAttribute(k_rowpass, cudaFuncAttributeMaxDynamicSharedMemorySize, 128000);
        cudaFuncSetAttribute(k_sink,    cudaFuncAttributeMaxDynamicSharedMemorySize, 34304 * 4);
        attr_done = true;
    }

    k_answers<<<1, 256>>>(stt, ttt);
    k_nop<<<1, 32>>>();               // launch-index padding so k_rowpass is
    k_nop<<<1, 32>>>();               // the profiled (4th) launch this round
    k_rowpass<<<2 * NBLK, 1024, 128000>>>(sl, tl);
    k_topk1<<<2 * NCHUNK, 512>>>();
    k_topk2<<<2, 1024>>>();
    k_q<<<2 * NROWS, 64>>>(sl, tl);
    k_W<<<dim3(8, 8, BB), dim3(16, 16)>>>();
    k_sink<<<32, 512, 34304 * 4>>>();
    k_final<<<1, 1>>>(ce, out);
}

// round 7
// speedup vs baseline: 1.3197x; 1.1525x over previous
#include <cuda_runtime.h>
#include <cuda_bf16.h>
#include <cstdint>

// Problem constants (fixed by the benchmark's reference)
#define BB 4
#define TT 1024
#define VV 32000
#define ANS 512
#define TOPK 50
#define IGNORE_ID (-100)
#define NROWS 2048            // B*ANS rows per tensor
#define NBLK 74               // blocks per tensor in rowpass
#define ROWS_PER_BLK 28       // 74*28 = 2072 >= 2048
#define F4_PER_ROW 8000       // 32000/4
#define NCHUNK 32             // top-k chunks per tensor
#define CHUNK 1000            // vocab per chunk
#define CLU 8                 // cluster size for Sinkhorn

// ---------------- device scratch (static, no runtime alloc) ----------------
__device__ int   g_start[8];                    // [tensor][b]
__device__ int   g_size[8];
__device__ float g_stats[2 * NROWS * 4];        // inv, mg, rZ, valid
__device__ float g_partial[2 * NBLK * VV];      // per-block vocab partial sums
__device__ unsigned long long g_ck[2 * NCHUNK * TOPK];  // chunk candidate keys
__device__ int   g_order[2 * TOPK];
__device__ float g_q[2 * BB * ANS * TOPK];      // softmax(p/2) per tensor
__device__ float g_W[BB * 512 * 512];
__device__ float g_Km[BB * 512 * 512];
__device__ float g_part[32];

// ---------------- helpers --------------------------------------------------
__device__ __forceinline__ uint32_t smem_u32(const void* p) {
    uint32_t a;
    asm("{ .reg .u64 t; cvta.to.shared.u64 t, %1; cvt.u32.u64 %0, t; }"
        : "=r"(a) : "l"(p));
    return a;
}
__device__ __forceinline__ float ld_remote(const float* p, uint32_t rank) {
    uint32_t a = smem_u32(p), ra;
    asm("mapa.shared::cluster.u32 %0, %1, %2;" : "=r"(ra) : "r"(a), "r"(rank));
    float v;
    asm volatile("ld.shared::cluster.f32 %0, [%1];" : "=f"(v) : "r"(ra));
    return v;
}
#define CLUSTER_SYNC() do { \
    asm volatile("barrier.cluster.arrive.aligned;" ::: "memory"); \
    asm volatile("barrier.cluster.wait.aligned;"   ::: "memory"); } while (0)

// Monotone flip: ascending uint order == ascending float order.
__device__ __forceinline__ uint32_t fflip(float x) {
    uint32_t u = __float_as_uint(x);
    return u ^ ((u >> 31) ? 0xFFFFFFFFu : 0x80000000u);
}
// Key: ascending u64 order -> value DESC, tie -> index ASC (matches argsort(-v)).
__device__ __forceinline__ unsigned long long mkkey(float v, uint32_t idx) {
    return ((unsigned long long)(~fflip(v)) << 32) | (unsigned long long)idx;
}

// Bitonic sort over smem keys. T threads, N = 2T keys.
template<int N, int T>
__device__ __forceinline__ void bitonic_sort(unsigned long long* keys, int t) {
    #pragma unroll 1
    for (int k = 2; k <= N; k <<= 1) {
        #pragma unroll 1
        for (int j = k >> 1; j > 0; j >>= 1) {
            int lo = t & (j - 1);
            int i  = ((t - lo) << 1) + lo;
            int p  = i | j;
            bool up = ((i & k) == 0);
            unsigned long long a = keys[i], b = keys[p];
            bool sw = up ? (a > b) : (a < b);
            if (sw) { keys[i] = b; keys[p] = a; }
            __syncthreads();
        }
    }
}

// ---------------- kernel 0: answers (start/size per tensor,batch) ----------
__global__ void k_answers(const int* __restrict__ st, const int* __restrict__ tt) {
    int tid = threadIdx.x;
    int w = tid >> 5, l = tid & 31;
    if (w < 8) {
        int tensor = w >> 2, b = w & 3;
        const int* tg = (tensor ? tt : st) + b * TT;
        int first = 0x7fffffff, cnt = 0;
        for (int j = l; j < TT; j += 32) {
            if (tg[j] != IGNORE_ID) { cnt++; first = min(first, j); }
        }
        #pragma unroll
        for (int o = 16; o; o >>= 1) {
            cnt += __shfl_down_sync(0xffffffffu, cnt, o);
            first = min(first, __shfl_down_sync(0xffffffffu, first, o));
        }
        if (l == 0) {
            g_size[tensor * 4 + b] = cnt;
            g_start[tensor * 4 + b] = (cnt > 0) ? first : 0;
        }
    }
}

// ---------------- kernel 1: per-row stats + softmax + vocab partial sums ---
// Accumulator lives in SMEM (thread-exclusive float4 slots); the row lives in
// registers only. 2 block barriers per row; final cross-warp reductions are
// done redundantly per-warp with xor-butterflies (no broadcast barrier).
__global__ __launch_bounds__(1024, 1) void k_rowpass(const float* __restrict__ sl,
                                                     const float* __restrict__ tl) {
    extern __shared__ float4 sacc[];           // 8000 float4 accumulator
    __shared__ float redS[32], redQ[32], redM[32], redZ[32];
    const int tensor = blockIdx.x / NBLK;
    const int local  = blockIdx.x % NBLK;
    const float* __restrict__ logits = tensor ? tl : sl;
    const int tid = threadIdx.x;
    const int w = tid >> 5, l = tid & 31;

    // zero the smem accumulator
    #pragma unroll
    for (int k = 0; k < 8; k++) {
        int f = tid + (k << 10);
        if (f < F4_PER_ROW) sacc[f] = make_float4(0.f, 0.f, 0.f, 0.f);
    }
    __syncthreads();

    int r0 = local * ROWS_PER_BLK;
    int r1 = min(r0 + ROWS_PER_BLK, NROWS);

    for (int r = r0; r < r1; r++) {
        int b = r >> 9, pos = r & 511;
        int sz = g_size[tensor * 4 + b];
        if (pos >= sz) {
            if (tid == 0) {
                float* st = &g_stats[(tensor * NROWS + r) * 4];
                st[0] = 0.f; st[1] = 0.f; st[2] = 0.f; st[3] = 0.f;
            }
            continue;
        }
        int trow = g_start[tensor * 4 + b] + pos;
        trow = max(0, min(trow, TT - 1));
        const float4* __restrict__ src =
            (const float4*)(logits + (size_t)(b * TT + trow) * VV);

        // sweep1: row -> registers, stats
        float4 x[8];
        float s = 0.f, q = 0.f, m = -3.402823466e38f;
        #pragma unroll
        for (int k = 0; k < 8; k++) {
            int f = tid + (k << 10);
            if (f < F4_PER_ROW) {
                float4 xx = src[f];
                x[k] = xx;
                s += (xx.x + xx.y) + (xx.z + xx.w);
                q += (xx.x * xx.x + xx.y * xx.y) + (xx.z * xx.z + xx.w * xx.w);
                m = fmaxf(fmaxf(m, fmaxf(xx.x, xx.y)), fmaxf(xx.z, xx.w));
            }
        }
        #pragma unroll
        for (int o = 16; o; o >>= 1) {
            s += __shfl_down_sync(0xffffffffu, s, o);
            q += __shfl_down_sync(0xffffffffu, q, o);
            m = fmaxf(m, __shfl_down_sync(0xffffffffu, m, o));
        }
        if (l == 0) { redS[w] = s; redQ[w] = q; redM[w] = m; }
        __syncthreads();                               // barrier 1
        // every warp redundantly reduces the 32 partials (butterfly)
        s = redS[l]; q = redQ[l]; m = redM[l];
        #pragma unroll
        for (int o = 16; o; o >>= 1) {
            s += __shfl_xor_sync(0xffffffffu, s, o);
            q += __shfl_xor_sync(0xffffffffu, q, o);
            m = fmaxf(m, __shfl_xor_sync(0xffffffffu, m, o));
        }
        float var = (q - s * s * (1.f / (float)VV)) * (1.f / (float)(VV - 1));
        var = fmaxf(var, 0.f);
        float inv = 1.f / fmaxf(sqrtf(var), 1e-6f);
        float mg = m * inv;

        // sweep2: e = exp(x*inv - mg) in registers, z
        float z = 0.f;
        #pragma unroll
        for (int k = 0; k < 8; k++) {
            int f = tid + (k << 10);
            if (f < F4_PER_ROW) {
                float4 xx = x[k];
                xx.x = __expf(fmaf(xx.x, inv, -mg));
                xx.y = __expf(fmaf(xx.y, inv, -mg));
                xx.z = __expf(fmaf(xx.z, inv, -mg));
                xx.w = __expf(fmaf(xx.w, inv, -mg));
                x[k] = xx;
                z += (xx.x + xx.y) + (xx.z + xx.w);
            }
        }
        #pragma unroll
        for (int o = 16; o; o >>= 1) z += __shfl_down_sync(0xffffffffu, z, o);
        if (l == 0) redZ[w] = z;
        __syncthreads();                               // barrier 2
        z = redZ[l];
        #pragma unroll
        for (int o = 16; o; o >>= 1) z += __shfl_xor_sync(0xffffffffu, z, o);
        float rZ = 1.f / z;

        // accumulate into smem (thread-exclusive slots, no conflicts)
        #pragma unroll
        for (int k = 0; k < 8; k++) {
            int f = tid + (k << 10);
            if (f < F4_PER_ROW) {
                float4 a = sacc[f];
                float4 e = x[k];
                a.x = fmaf(e.x, rZ, a.x);
                a.y = fmaf(e.y, rZ, a.y);
                a.z = fmaf(e.z, rZ, a.z);
                a.w = fmaf(e.w, rZ, a.w);
                sacc[f] = a;
            }
        }
        if (tid == 0) {
            float* st = &g_stats[(tensor * NROWS + r) * 4];
            st[0] = inv; st[1] = mg; st[2] = rZ; st[3] = 1.f;
        }
    }
    __syncthreads();
    // flush deterministic per-block partials
    float4* gp = (float4*)&g_partial[(size_t)(tensor * NBLK + local) * VV];
    #pragma unroll
    for (int k = 0; k < 8; k++) {
        int f = tid + (k << 10);
        if (f < F4_PER_ROW) gp[f] = sacc[f];
    }
}

// ---------------- kernel 2: chunk reduce + bitonic local top-50 ------------
// grid = 2*NCHUNK blocks, 512 threads. Chunk c covers vocab [c*1000, (c+1)*1000).
__global__ __launch_bounds__(512, 2) void k_topk1() {
    __shared__ unsigned long long keys[1024];
    int t = blockIdx.x >> 5;
    int c = blockIdx.x & 31;
    int tid = threadIdx.x;
    int vbase = c * CHUNK;

    // reduce the 74 per-block partials (coalesced) and build keys
    #pragma unroll
    for (int k = 0; k < 2; k++) {
        int vl = tid + (k << 9);
        if (vl < CHUNK) {
            const float* p = &g_partial[(size_t)t * NBLK * VV + vbase + vl];
            float s = 0.f;
            #pragma unroll 2
            for (int lb = 0; lb < NBLK; lb++) s += p[(size_t)lb * VV];
            keys[vl] = mkkey(s, (uint32_t)(vbase + vl));
        } else {
            keys[vl] = 0xFFFFFFFFFFFFFFFFull;   // pad: sorts last
        }
    }
    __syncthreads();
    bitonic_sort<1024, 512>(keys, tid);
    if (tid < TOPK)
        g_ck[(t * NCHUNK + c) * TOPK + tid] = keys[tid];
}

// ---------------- kernel 3: bitonic merge 1600 candidates -> top-50 --------
__global__ __launch_bounds__(1024, 1) void k_topk2() {
    __shared__ unsigned long long keys[2048];
    int t = blockIdx.x;
    int tid = threadIdx.x;
    const int NC = NCHUNK * TOPK;   // 1600
    #pragma unroll
    for (int k = 0; k < 2; k++) {
        int s = tid + (k << 10);
        keys[s] = (s < NC) ? g_ck[t * NC + s] : 0xFFFFFFFFFFFFFFFFull;
    }
    __syncthreads();
    bitonic_sort<2048, 1024>(keys, tid);
    if (tid < TOPK)
        g_order[t * TOPK + tid] = (int)(keys[tid] & 0xFFFFFFFFull);
}

// ---------------- kernel 4: gather top-50 probs, softmax(p/2) --------------
__global__ void k_q(const float* __restrict__ sl, const float* __restrict__ tl) {
    __shared__ float sb[64];
    int id = blockIdx.x;
    int tensor = id >> 11;
    int r = id & 2047;
    int b = r >> 9, pos = r & 511;
    int tid = threadIdx.x;
    const float* __restrict__ logits = tensor ? tl : sl;
    const float* st = &g_stats[(tensor * NROWS + r) * 4];
    float inv = st[0], mg = st[1], rZ = st[2], val = st[3];
    int trow = g_start[tensor * 4 + b] + pos;
    trow = max(0, min(trow, TT - 1));
    float p = 0.f;
    if (tid < TOPK && val > 0.f) {
        int vv = g_order[tensor * TOPK + tid];
        float x = logits[(size_t)(b * TT + trow) * VV + vv];
        p = __expf(fmaf(x, inv, -mg)) * rZ;
    }
    float a = (tid < TOPK) ? 0.5f * p : -3.402823466e38f;   // /SINK_T
    sb[tid] = a; __syncthreads();
    for (int o = 32; o; o >>= 1) { if (tid < o) sb[tid] = fmaxf(sb[tid], sb[tid + o]); __syncthreads(); }
    float amax = sb[0]; __syncthreads();
    float e = (tid < TOPK) ? __expf(a - amax) : 0.f;
    sb[tid] = e; __syncthreads();
    for (int o = 32; o; o >>= 1) { if (tid < o) sb[tid] = sb[tid] + sb[tid + o]; __syncthreads(); }
    float ssum = sb[0];
    if (tid < TOPK)
        g_q[((size_t)(tensor * BB + b) * ANS + pos) * TOPK + tid] = e / ssum;
}

// ---------------- kernel 5: W, K=max(exp(-2W),1e-30) -----------------------
__device__ __forceinline__ float expK(float wv) {
    return fmaxf(__expf(-2.f * wv), 1e-30f);
}
__global__ void k_W() {
    __shared__ float xs[TOPK][64];
    __shared__ float ys[TOPK][64];
    int b = blockIdx.z;
    int i0 = blockIdx.x * 64, j0 = blockIdx.y * 64;
    int tx = threadIdx.x, ty = threadIdx.y;
    int tid = ty * 16 + tx;
    for (int e = tid; e < 64 * TOPK; e += 256) {
        int rr = e / TOPK, kk = e - rr * TOPK;
        xs[kk][rr] = g_q[((size_t)(0 * BB + b) * ANS + (i0 + rr)) * TOPK + kk];
        ys[kk][rr] = g_q[((size_t)(1 * BB + b) * ANS + (j0 + rr)) * TOPK + kk];
    }
    __syncthreads();
    float acc[4][4];
    #pragma unroll
    for (int i = 0; i < 4; i++)
        #pragma unroll
        for (int j = 0; j < 4; j++) acc[i][j] = 0.f;
    for (int k = 0; k < TOPK; k++) {
        float4 a = *(const float4*)&xs[k][tx * 4];
        float4 c = *(const float4*)&ys[k][ty * 4];
        acc[0][0] += fabsf(a.x - c.x); acc[0][1] += fabsf(a.x - c.y);
        acc[0][2] += fabsf(a.x - c.z); acc[0][3] += fabsf(a.x - c.w);
        acc[1][0] += fabsf(a.y - c.x); acc[1][1] += fabsf(a.y - c.y);
        acc[1][2] += fabsf(a.y - c.z); acc[1][3] += fabsf(a.y - c.w);
        acc[2][0] += fabsf(a.z - c.x); acc[2][1] += fabsf(a.z - c.y);
        acc[2][2] += fabsf(a.z - c.z); acc[2][3] += fabsf(a.z - c.w);
        acc[3][0] += fabsf(a.w - c.x); acc[3][1] += fabsf(a.w - c.y);
        acc[3][2] += fabsf(a.w - c.z); acc[3][3] += fabsf(a.w - c.w);
    }
    #pragma unroll
    for (int ii = 0; ii < 4; ii++) {
        int i = i0 + tx * 4 + ii;
        float4 wv = make_float4(acc[ii][0], acc[ii][1], acc[ii][2], acc[ii][3]);
        size_t base = ((size_t)(b * 512) + i) * 512 + j0 + ty * 4;
        *(float4*)&g_W[base] = wv;
        *(float4*)&g_Km[base] = make_float4(expK(wv.x), expK(wv.y), expK(wv.z), expK(wv.w));
    }
}

// ---------------- kernel 6: fused Sinkhorn (10 iters) + loss ---------------
// Grid: 32 blocks = 4 batches x 8-CTA clusters. Each CTA owns 64 rows of K.
// Only the OWN u segment is ever needed (u-step, v-partial, loss), so no
// u exchange; v is rebuilt redundantly per CTA from DSMEM ps partials.
__global__ __cluster_dims__(CLU, 1, 1) __launch_bounds__(512, 1)
void k_sink() {
    extern __shared__ float sm[];
    float* Ks = sm;                 // 64*512 = 32768 floats (own K rows)
    float* us = sm + 32768;         // 512 (only own 64-segment used)
    float* vs = sm + 33280;         // 512
    float* ps = sm + 33792;         // 512 (partial for v-step)
    __shared__ float lred[16];

    uint32_t rank;
    asm("mov.u32 %0, %%cluster_ctarank;" : "=r"(rank));
    int b = blockIdx.x >> 3;
    int tid = threadIdx.x;
    int w = tid >> 5, l = tid & 31;

    // load own K block (rows [rank*64, rank*64+64))
    const float4* src = (const float4*)(g_Km + ((size_t)(b * 512) + rank * 64) * 512);
    float4* dst = (float4*)Ks;
    for (int i = tid; i < 64 * 512 / 4; i += 512) dst[i] = src[i];
    us[tid] = 1.f; vs[tid] = 1.f;
    __syncthreads();

    for (int it = 0; it < 10; it++) {
        // ---- u-step (own rows): u_i <- u_i / max(u_i*(K v)_i, 1e-10)
        #pragma unroll
        for (int rr = 0; rr < 4; rr++) {
            int i = w * 4 + rr;                       // local row 0..63
            const float4* row = (const float4*)(Ks + i * 512);
            float d = 0.f;
            #pragma unroll
            for (int c = 0; c < 4; c++) {
                int f = l + (c << 5);
                float4 kv = row[f];
                int j = f << 2;
                d += kv.x * vs[j] + kv.y * vs[j + 1] + kv.z * vs[j + 2] + kv.w * vs[j + 3];
            }
            #pragma unroll
            for (int o = 16; o; o >>= 1) d += __shfl_down_sync(0xffffffffu, d, o);
            if (l == 0) {
                int gi = rank * 64 + i;
                float uu = us[gi];
                us[gi] = uu / fmaxf(uu * d, 1e-10f);
            }
        }
        __syncthreads();
        // ---- v-step partial: ps[j] = sum_{i in own rows} K[i][j] * u[own i]
        {
            float s = 0.f;
            #pragma unroll 8
            for (int i = 0; i < 64; i++)
                s = fmaf(Ks[i * 512 + tid], us[rank * 64 + i], s);
            ps[tid] = s;
        }
        __syncthreads();
        CLUSTER_SYNC();                               // publish ps to cluster
        // ---- v-reduce (each CTA redundantly computes full new v)
        {
            float s = ps[tid];
            #pragma unroll
            for (int c = 0; c < CLU; c++) {
                if ((uint32_t)c != rank) s += ld_remote(&ps[tid], (uint32_t)c);
            }
            float vv = vs[tid];
            vs[tid] = vv / fmaxf(vv * s, 1e-10f);
        }
        CLUSTER_SYNC();                               // all remote ps reads done
    }

    // ---- loss: sum over own rows of u_i * K_ij * W_ij * v_j
    const float* Wg = g_W + ((size_t)(b * 512) + rank * 64) * 512;
    float lacc = 0.f;
    #pragma unroll
    for (int rr = 0; rr < 4; rr++) {
        int i = w * 4 + rr;
        const float4* rowK = (const float4*)(Ks + i * 512);
        const float4* rowW = (const float4*)(Wg + (size_t)i * 512);
        float d = 0.f;
        #pragma unroll
        for (int c = 0; c < 4; c++) {
            int f = l + (c << 5);
            float4 kv = rowK[f];
            float4 wv = rowW[f];
            int j = f << 2;
            d += kv.x * wv.x * vs[j] + kv.y * wv.y * vs[j + 1]
               + kv.z * wv.z * vs[j + 2] + kv.w * wv.w * vs[j + 3];
        }
        #pragma unroll
        for (int o = 16; o; o >>= 1) d += __shfl_down_sync(0xffffffffu, d, o);
        if (l == 0) lacc += us[rank * 64 + i] * d;
    }
    if (l == 0) lred[w] = lacc;
    __syncthreads();
    if (tid == 0) {
        float s = 0.f;
        #pragma unroll
        for (int k = 0; k < 16; k++) s += lred[k];
        g_part[blockIdx.x] = s;
    }
    CLUSTER_SYNC();   // no CTA exits while peers may still read its smem
}

// ---------------- kernel 7: final scalar -----------------------------------
__global__ void k_final(const float* __restrict__ ce, float* __restrict__ out) {
    float s = 0.f;
    for (int i = 0; i < 32; i++) s += g_part[i];
    out[0] = ce[0] + 0.001f * s;   // CE_W=1, KD_W=1
}

// ---------------- launcher -------------------------------------------------
extern "C" void kernel_launch(void* const* d_in, const int* in_sizes, int n_in,
                              void* d_out, int out_size) {
    const float* sl  = (const float*)d_in[0];
    const float* tl  = (const float*)d_in[1];
    const float* ce  = (const float*)d_in[2];
    const int*   stt = (const int*)d_in[3];
    const int*   ttt = (const int*)d_in[4];
    float* out = (float*)d_out;

    static bool attr_done = false;
    if (!attr_done) {
        cudaFuncSetAttribute(k_rowpass, cudaFuncAttributeMaxDynamicSharedMemorySize, 128000);
        cudaFuncSetAttribute(k_sink,    cudaFuncAttributeMaxDynamicSharedMemorySize, 34304 * 4);
        attr_done = true;
    }

    k_answers<<<1, 256>>>(stt, ttt);
    k_rowpass<<<2 * NBLK, 1024, 128000>>>(sl, tl);
    k_topk1<<<2 * NCHUNK, 512>>>();
    k_topk2<<<2, 1024>>>();
    k_q<<<2 * NROWS, 64>>>(sl, tl);
    k_W<<<dim3(8, 8, BB), dim3(16, 16)>>>();
    k_sink<<<32, 512, 34304 * 4>>>();
    k_final<<<1, 1>>>(ce, out);
}